// round 1
// baseline (speedup 1.0000x reference)
#include <cuda_runtime.h>
#include <math.h>

#define B 8
#define L 2048
#define D 256
#define NEG_INF -1e10f

// ---------------- device scratch (static, no allocations) ----------------
__device__ float g_predW[B * L * D];          // 16 MB
__device__ float g_pred_sq[B * L];
__device__ float g_src_sq[B * L];
__device__ float g_cost[(size_t)B * L * L];   // 134 MB
__device__ float g_tr[(size_t)B * L * L];     // 134 MB
__device__ float g_rowval[B * L];

// ---------------- kernel 1: row squared norms ----------------
__global__ void sqnorms_kernel(const float* __restrict__ hx,
                               const float* __restrict__ hy) {
    int gtid = blockIdx.x * blockDim.x + threadIdx.x;
    int warp = gtid >> 5;
    int lane = gtid & 31;
    if (warp >= B * L) return;
    const float* xr = hx + (size_t)warp * D;
    const float* yr = hy + (size_t)warp * D;
    float sx = 0.f, sy = 0.f;
    #pragma unroll
    for (int i = lane; i < D; i += 32) {
        float vx = xr[i]; sx += vx * vx;
        float vy = yr[i]; sy += vy * vy;
    }
    #pragma unroll
    for (int o = 16; o > 0; o >>= 1) {
        sx += __shfl_down_sync(0xffffffffu, sx, o);
        sy += __shfl_down_sync(0xffffffffu, sy, o);
    }
    if (lane == 0) {
        g_src_sq[warp] = sx;
        g_pred_sq[warp] = sy;
    }
}

// ---------------- kernel 2: predW = hy @ W  (M=B*L, K=D, N=D) ----------------
__global__ void __launch_bounds__(256, 2) predw_gemm_kernel(
    const float* __restrict__ hy, const float* __restrict__ W) {
    __shared__ float sA[32][132];   // transposed A tile [k][m]
    __shared__ float sB[32][68];    // B tile [k][n]
    int tid = threadIdx.x;
    int tx = tid & 15, ty = tid >> 4;
    int m0 = blockIdx.y * 128;
    int n0 = blockIdx.x * 64;
    const float* Ag = hy + (size_t)m0 * D;
    float acc[8][4];
    #pragma unroll
    for (int i = 0; i < 8; i++)
        #pragma unroll
        for (int j = 0; j < 4; j++) acc[i][j] = 0.f;

    for (int kk = 0; kk < D; kk += 32) {
        #pragma unroll
        for (int i = 0; i < 4; i++) {
            int idx = tid + i * 256;
            int r = idx >> 3, c = idx & 7;
            float4 v = *(const float4*)(Ag + (size_t)r * D + kk + c * 4);
            sA[c * 4 + 0][r] = v.x; sA[c * 4 + 1][r] = v.y;
            sA[c * 4 + 2][r] = v.z; sA[c * 4 + 3][r] = v.w;
        }
        #pragma unroll
        for (int i = 0; i < 2; i++) {
            int idx = tid + i * 256;
            int r = idx >> 4, c = idx & 15;
            float4 v = *(const float4*)(W + (size_t)(kk + r) * D + n0 + c * 4);
            *(float4*)&sB[r][c * 4] = v;
        }
        __syncthreads();
        #pragma unroll
        for (int k = 0; k < 32; k++) {
            float a[8], bv[4];
            float4 a0 = *(float4*)&sA[k][ty * 8];
            float4 a1 = *(float4*)&sA[k][ty * 8 + 4];
            a[0] = a0.x; a[1] = a0.y; a[2] = a0.z; a[3] = a0.w;
            a[4] = a1.x; a[5] = a1.y; a[6] = a1.z; a[7] = a1.w;
            float4 b0 = *(float4*)&sB[k][tx * 4];
            bv[0] = b0.x; bv[1] = b0.y; bv[2] = b0.z; bv[3] = b0.w;
            #pragma unroll
            for (int i = 0; i < 8; i++)
                #pragma unroll
                for (int j = 0; j < 4; j++)
                    acc[i][j] += a[i] * bv[j];
        }
        __syncthreads();
    }
    #pragma unroll
    for (int i = 0; i < 8; i++) {
        float4 v = make_float4(acc[i][0], acc[i][1], acc[i][2], acc[i][3]);
        *(float4*)(g_predW + (size_t)(m0 + ty * 8 + i) * D + n0 + tx * 4) = v;
    }
}

// ---------------- kernel 3: fused dual GEMM + epilogue ----------------
// per batch: cross[p,s] = pred[p,:]·src[s,:]; trv[p,s] = predW[p,:]·src[s,:]
// cost = sqrt(max(psq+ssq-2*cross,0)); tr = mask ? trv : NEG_INF
__global__ void __launch_bounds__(256, 2) fused_scores_kernel(
    const float* __restrict__ hx, const float* __restrict__ hy,
    const float* __restrict__ xmask, const float* __restrict__ ymask) {
    __shared__ float sP[32][132];   // pred   transposed [k][p]
    __shared__ float sQ[32][132];   // predW  transposed [k][p]
    __shared__ float sS[32][68];    // src    transposed [k][s]
    int tid = threadIdx.x;
    int tx = tid & 15, ty = tid >> 4;
    int b = blockIdx.z;
    int p0 = blockIdx.y * 128;
    int s0 = blockIdx.x * 64;
    const float* Pg = hy      + ((size_t)b * L + p0) * D;
    const float* Qg = g_predW + ((size_t)b * L + p0) * D;
    const float* Sg = hx      + ((size_t)b * L + s0) * D;

    float ac[8][4], at[8][4];
    #pragma unroll
    for (int i = 0; i < 8; i++)
        #pragma unroll
        for (int j = 0; j < 4; j++) { ac[i][j] = 0.f; at[i][j] = 0.f; }

    for (int kk = 0; kk < D; kk += 32) {
        #pragma unroll
        for (int i = 0; i < 4; i++) {
            int idx = tid + i * 256;
            int r = idx >> 3, c = idx & 7;
            float4 v = *(const float4*)(Pg + (size_t)r * D + kk + c * 4);
            sP[c * 4 + 0][r] = v.x; sP[c * 4 + 1][r] = v.y;
            sP[c * 4 + 2][r] = v.z; sP[c * 4 + 3][r] = v.w;
            float4 w = *(const float4*)(Qg + (size_t)r * D + kk + c * 4);
            sQ[c * 4 + 0][r] = w.x; sQ[c * 4 + 1][r] = w.y;
            sQ[c * 4 + 2][r] = w.z; sQ[c * 4 + 3][r] = w.w;
        }
        #pragma unroll
        for (int i = 0; i < 2; i++) {
            int idx = tid + i * 256;
            int r = idx >> 3, c = idx & 7;
            float4 v = *(const float4*)(Sg + (size_t)r * D + kk + c * 4);
            sS[c * 4 + 0][r] = v.x; sS[c * 4 + 1][r] = v.y;
            sS[c * 4 + 2][r] = v.z; sS[c * 4 + 3][r] = v.w;
        }
        __syncthreads();
        #pragma unroll
        for (int k = 0; k < 32; k++) {
            float a[8], q[8], s[4];
            float4 a0 = *(float4*)&sP[k][ty * 8];
            float4 a1 = *(float4*)&sP[k][ty * 8 + 4];
            a[0] = a0.x; a[1] = a0.y; a[2] = a0.z; a[3] = a0.w;
            a[4] = a1.x; a[5] = a1.y; a[6] = a1.z; a[7] = a1.w;
            float4 q0 = *(float4*)&sQ[k][ty * 8];
            float4 q1 = *(float4*)&sQ[k][ty * 8 + 4];
            q[0] = q0.x; q[1] = q0.y; q[2] = q0.z; q[3] = q0.w;
            q[4] = q1.x; q[5] = q1.y; q[6] = q1.z; q[7] = q1.w;
            float4 b0 = *(float4*)&sS[k][tx * 4];
            s[0] = b0.x; s[1] = b0.y; s[2] = b0.z; s[3] = b0.w;
            #pragma unroll
            for (int i = 0; i < 8; i++)
                #pragma unroll
                for (int j = 0; j < 4; j++) {
                    ac[i][j] += a[i] * s[j];
                    at[i][j] += q[i] * s[j];
                }
        }
        __syncthreads();
    }

    // epilogue
    float ps[8], pm[8];
    #pragma unroll
    for (int i = 0; i < 8; i++) {
        int p = p0 + ty * 8 + i;
        ps[i] = g_pred_sq[b * L + p];
        pm[i] = ymask[b * L + p];
    }
    float ssq[4], smk[4];
    #pragma unroll
    for (int j = 0; j < 4; j++) {
        int s = s0 + tx * 4 + j;
        ssq[j] = g_src_sq[b * L + s];
        smk[j] = xmask[b * L + s];
    }
    #pragma unroll
    for (int i = 0; i < 8; i++) {
        int p = p0 + ty * 8 + i;
        size_t base = ((size_t)(b * L + p)) * L + s0 + tx * 4;
        float4 vc, vt;
        float c0, t0;
        #pragma unroll
        for (int j = 0; j < 4; j++) {
            float cr = ac[i][j];
            float d2 = ps[i] + ssq[j] - 2.f * cr;
            c0 = sqrtf(fmaxf(d2, 0.f));
            t0 = (pm[i] * smk[j] != 0.f) ? at[i][j] : NEG_INF;
            if (j == 0) { vc.x = c0; vt.x = t0; }
            else if (j == 1) { vc.y = c0; vt.y = t0; }
            else if (j == 2) { vc.z = c0; vt.z = t0; }
            else { vc.w = c0; vt.w = t0; }
        }
        *(float4*)(g_cost + base) = vc;
        *(float4*)(g_tr + base) = vt;
    }
}

// ---------------- kernel 4: per-row online softmax * cost ----------------
__global__ void row_softmax_kernel() {
    int row = blockIdx.x;                       // 0 .. B*L-1
    const float* trp = g_tr + (size_t)row * L;
    const float* cp = g_cost + (size_t)row * L;
    int tid = threadIdx.x;
    float m = -INFINITY, Z = 0.f, N = 0.f;
    for (int i = tid; i < L; i += 256) {
        float t = trp[i], c = cp[i];
        float mn = fmaxf(m, t);
        float sc = __expf(m - mn);
        float e = __expf(t - mn);
        Z = Z * sc + e;
        N = N * sc + e * c;
        m = mn;
    }
    __shared__ float sm[256], sz[256], sn[256];
    sm[tid] = m; sz[tid] = Z; sn[tid] = N;
    __syncthreads();
    for (int o = 128; o > 0; o >>= 1) {
        if (tid < o) {
            float m2 = sm[tid + o], z2 = sz[tid + o], n2 = sn[tid + o];
            float mn = fmaxf(sm[tid], m2);
            float s1 = __expf(sm[tid] - mn);
            float s2 = __expf(m2 - mn);
            sz[tid] = sz[tid] * s1 + z2 * s2;
            sn[tid] = sn[tid] * s1 + n2 * s2;
            sm[tid] = mn;
        }
        __syncthreads();
    }
    if (tid == 0) g_rowval[row] = sn[0] / sz[0];
}

// ---------------- kernel 5: deterministic final reduction ----------------
__global__ void finalize_kernel(const float* __restrict__ xmask,
                                const float* __restrict__ ymask,
                                float* __restrict__ out) {
    __shared__ float red[256];
    __shared__ float inv[B];
    int tid = threadIdx.x;
    float s = 0.f;
    for (int i = tid; i < B * L; i += 256) s += g_rowval[i];
    red[tid] = s;
    __syncthreads();
    for (int o = 128; o > 0; o >>= 1) {
        if (tid < o) red[tid] += red[tid + o];
        __syncthreads();
    }
    if (tid < B) {
        float n1 = 0.f, n2 = 0.f;
        for (int i = 0; i < L; i++) {
            n1 += ymask[tid * L + i];
            n2 += xmask[tid * L + i];
        }
        inv[tid] = 1.f / (n1 * n2);
    }
    __syncthreads();
    if (tid == 0) {
        float F = 0.f;
        for (int b = 0; b < B; b++) F += inv[b];
        out[0] = red[0] * F / (float)(B * B);
    }
}

// ---------------- launch ----------------
extern "C" void kernel_launch(void* const* d_in, const int* in_sizes, int n_in,
                              void* d_out, int out_size) {
    const float* hx = (const float*)d_in[0];   // h_x [B,L,D]
    const float* hy = (const float*)d_in[1];   // h_y [B,L,D]
    const float* xm = (const float*)d_in[2];   // x_mask [B,L]
    const float* ym = (const float*)d_in[3];   // y_mask [B,L]
    const float* W  = (const float*)d_in[4];   // W [D,D]
    float* out = (float*)d_out;

    sqnorms_kernel<<<(B * L * 32 + 255) / 256, 256>>>(hx, hy);
    predw_gemm_kernel<<<dim3(D / 64, (B * L) / 128), 256>>>(hy, W);
    fused_scores_kernel<<<dim3(L / 64, L / 128, B), 256>>>(hx, hy, xm, ym);
    row_softmax_kernel<<<B * L, 256>>>();
    finalize_kernel<<<1, 256>>>(xm, ym, out);
}

// round 3
// speedup vs baseline: 2.3974x; 2.3974x over previous
#include <cuda_runtime.h>
#include <math.h>
#include <cstdint>

#define B 8
#define L 2048
#define D 256
#define NEG_INF -1e10f

// ---------------- device scratch (static, no allocations) ----------------
__device__ float g_predW[B * L * D];          // 16 MB (tf32-rounded)
__device__ float g_hx_r[B * L * D];           // 16 MB (tf32-rounded src)
__device__ float g_hy_r[B * L * D];           // 16 MB (tf32-rounded pred)
__device__ float g_pred_sq[B * L];
__device__ float g_src_sq[B * L];
__device__ float g_stat_m[B * 16 * L];        // per (b, s_tile, p) stats
__device__ float g_stat_z[B * 16 * L];
__device__ float g_stat_n[B * 16 * L];
__device__ float g_rowval[B * L];

// ---------------- PTX helpers ----------------
__device__ __forceinline__ uint32_t smem_u32(const void* p) {
    uint32_t a;
    asm("{ .reg .u64 t; cvta.to.shared.u64 t, %1; cvt.u32.u64 %0, t; }" : "=r"(a) : "l"(p));
    return a;
}
__device__ __forceinline__ float round_tf32(float v) {
    uint32_t u;
    asm("cvt.rna.tf32.f32 %0, %1;" : "=r"(u) : "f"(v));
    return __uint_as_float(u);
}

// ---------------- kernel 1: row sq-norms + tf32 rounding (fused) ----------------
__global__ void sqnorms_round_kernel(const float* __restrict__ hx,
                                     const float* __restrict__ hy) {
    int gtid = blockIdx.x * blockDim.x + threadIdx.x;
    int row = gtid >> 5;
    int lane = gtid & 31;
    if (row >= B * L) return;
    const float* xr = hx + (size_t)row * D;
    const float* yr = hy + (size_t)row * D;
    float* xo = g_hx_r + (size_t)row * D;
    float* yo = g_hy_r + (size_t)row * D;
    float sx = 0.f, sy = 0.f;
    #pragma unroll
    for (int i = lane; i < D; i += 32) {
        float vx = xr[i]; sx += vx * vx; xo[i] = round_tf32(vx);
        float vy = yr[i]; sy += vy * vy; yo[i] = round_tf32(vy);
    }
    #pragma unroll
    for (int o = 16; o > 0; o >>= 1) {
        sx += __shfl_down_sync(0xffffffffu, sx, o);
        sy += __shfl_down_sync(0xffffffffu, sy, o);
    }
    if (lane == 0) { g_src_sq[row] = sx; g_pred_sq[row] = sy; }
}

// ---------------- kernel 2: predW = hy @ W, tf32-rounded store ----------------
__global__ void __launch_bounds__(256, 2) predw_gemm_kernel(
    const float* __restrict__ hy, const float* __restrict__ W) {
    __shared__ float sA[32][132];
    __shared__ float sB[32][68];
    int tid = threadIdx.x;
    int tx = tid & 15, ty = tid >> 4;
    int m0 = blockIdx.y * 128;
    int n0 = blockIdx.x * 64;
    const float* Ag = hy + (size_t)m0 * D;
    float acc[8][4];
    #pragma unroll
    for (int i = 0; i < 8; i++)
        #pragma unroll
        for (int j = 0; j < 4; j++) acc[i][j] = 0.f;

    for (int kk = 0; kk < D; kk += 32) {
        #pragma unroll
        for (int i = 0; i < 4; i++) {
            int idx = tid + i * 256;
            int r = idx >> 3, c = idx & 7;
            float4 v = *(const float4*)(Ag + (size_t)r * D + kk + c * 4);
            sA[c * 4 + 0][r] = v.x; sA[c * 4 + 1][r] = v.y;
            sA[c * 4 + 2][r] = v.z; sA[c * 4 + 3][r] = v.w;
        }
        #pragma unroll
        for (int i = 0; i < 2; i++) {
            int idx = tid + i * 256;
            int r = idx >> 4, c = idx & 15;
            float4 v = *(const float4*)(W + (size_t)(kk + r) * D + n0 + c * 4);
            *(float4*)&sB[r][c * 4] = v;
        }
        __syncthreads();
        #pragma unroll
        for (int k = 0; k < 32; k++) {
            float a[8], bv[4];
            float4 a0 = *(float4*)&sA[k][ty * 8];
            float4 a1 = *(float4*)&sA[k][ty * 8 + 4];
            a[0] = a0.x; a[1] = a0.y; a[2] = a0.z; a[3] = a0.w;
            a[4] = a1.x; a[5] = a1.y; a[6] = a1.z; a[7] = a1.w;
            float4 b0 = *(float4*)&sB[k][tx * 4];
            bv[0] = b0.x; bv[1] = b0.y; bv[2] = b0.z; bv[3] = b0.w;
            #pragma unroll
            for (int i = 0; i < 8; i++)
                #pragma unroll
                for (int j = 0; j < 4; j++)
                    acc[i][j] += a[i] * bv[j];
        }
        __syncthreads();
    }
    #pragma unroll
    for (int i = 0; i < 8; i++) {
        float4 v = make_float4(round_tf32(acc[i][0]), round_tf32(acc[i][1]),
                               round_tf32(acc[i][2]), round_tf32(acc[i][3]));
        *(float4*)(g_predW + (size_t)(m0 + ty * 8 + i) * D + n0 + tx * 4) = v;
    }
}

// ---------------- kernel 3: tcgen05 tf32 dual-GEMM + fused flash epilogue ----
#define SM_SSQ   64
#define SM_SMASK 576
#define SM_BUF   2048
#define OP_BYTES 32768
#define STAGE_BYTES (3 * OP_BYTES)
#define SMEM_TOTAL (SM_BUF + 2 * STAGE_BYTES)

__device__ __forceinline__ void load_chunk64(const float* __restrict__ gbase,
                                             char* smem, int off, int tid) {
    #pragma unroll
    for (int i = 0; i < 16; i++) {
        int idx = tid + i * 128;
        int r = idx >> 4;
        int c = idx & 15;
        float4 v = *(const float4*)(gbase + (size_t)r * D + c * 4);
        int grp = c >> 3;
        uint32_t byte = r * 128 + (c & 7) * 16;
        uint32_t sw = byte ^ ((byte >> 3) & 0x70);
        *(float4*)(smem + off + grp * 16384 + sw) = v;
    }
}

#if defined(__CUDA_ARCH_SPECIFIC__)
// ---- sm_103a-specific pieces (tcgen05) ----
#define TC_ALLOC(sm, n)   asm volatile("tcgen05.alloc.cta_group::1.sync.aligned.shared::cta.b32 [%0], %1;" :: "r"(sm), "r"(n) : "memory")
#define TC_DEALLOC(t, n)  asm volatile("tcgen05.dealloc.cta_group::1.sync.aligned.b32 %0, %1;" :: "r"(t), "r"(n))
#define TC_RELINQ()       asm volatile("tcgen05.relinquish_alloc_permit.cta_group::1.sync.aligned;")
#define TC_COMMIT(mb)     asm volatile("tcgen05.commit.cta_group::1.mbarrier::arrive::one.shared::cluster.b64 [%0];" :: "r"(mb) : "memory")
#define TC_FENCE_AFTER()  asm volatile("tcgen05.fence::after_thread_sync;" ::: "memory")
#define TC_WAIT_LD()      asm volatile("tcgen05.wait::ld.sync.aligned;" ::: "memory")
#define MBAR_INIT(mb, c)  asm volatile("mbarrier.init.shared.b64 [%0], %1;" :: "r"(mb), "r"(c) : "memory")
#define MBAR_INVAL(mb)    asm volatile("mbarrier.inval.shared.b64 [%0];" :: "r"(mb) : "memory")
#define FENCE_ASYNC()     asm volatile("fence.proxy.async.shared::cta;" ::: "memory")

#define MBAR_WAIT0(mb) do {                                                            \
    uint32_t _m = (mb), _d;                                                            \
    asm volatile("{\n\t.reg .pred p;\n\t"                                              \
        "mbarrier.try_wait.parity.acquire.cta.shared::cta.b64 p, [%1], 0;\n\t"         \
        "selp.b32 %0, 1, 0, p;\n\t}" : "=r"(_d) : "r"(_m) : "memory");                 \
    if (!_d) {                                                                          \
        asm volatile("{\n\t.reg .pred P1;\n\tWL_%=:\n\t"                               \
            "mbarrier.try_wait.parity.acquire.cta.shared::cta.b64 P1, [%0], 0, 0x989680;\n\t" \
            "@P1 bra.uni WD_%=;\n\tbra.uni WL_%=;\n\tWD_%=:\n\t}"                      \
            :: "r"(_m) : "memory");                                                     \
    } } while (0)

#define LDTM32(r, addr)                                                                \
    asm volatile("tcgen05.ld.sync.aligned.32x32b.x32.b32 "                             \
        "{%0,%1,%2,%3,%4,%5,%6,%7,%8,%9,%10,%11,%12,%13,%14,%15,"                      \
        "%16,%17,%18,%19,%20,%21,%22,%23,%24,%25,%26,%27,%28,%29,%30,%31}, [%32];"     \
        : "=r"((r)[0]),"=r"((r)[1]),"=r"((r)[2]),"=r"((r)[3]),                          \
          "=r"((r)[4]),"=r"((r)[5]),"=r"((r)[6]),"=r"((r)[7]),                          \
          "=r"((r)[8]),"=r"((r)[9]),"=r"((r)[10]),"=r"((r)[11]),                        \
          "=r"((r)[12]),"=r"((r)[13]),"=r"((r)[14]),"=r"((r)[15]),                      \
          "=r"((r)[16]),"=r"((r)[17]),"=r"((r)[18]),"=r"((r)[19]),                      \
          "=r"((r)[20]),"=r"((r)[21]),"=r"((r)[22]),"=r"((r)[23]),                      \
          "=r"((r)[24]),"=r"((r)[25]),"=r"((r)[26]),"=r"((r)[27]),                      \
          "=r"((r)[28]),"=r"((r)[29]),"=r"((r)[30]),"=r"((r)[31])                       \
        : "r"(addr))

__device__ __forceinline__ uint32_t elect_one() {
    uint32_t pred;
    asm volatile("{\n\t.reg .pred p;\n\telect.sync _|p, 0xFFFFFFFF;\n\tselp.b32 %0, 1, 0, p;\n\t}" : "=r"(pred));
    return pred;
}
__device__ __forceinline__ void mma_tf32_ss(uint32_t d_tmem, uint64_t a_desc,
                                            uint64_t b_desc, uint32_t idesc, uint32_t en) {
    asm volatile(
        "{\n\t.reg .pred p;\n\tsetp.ne.u32 p, %5, 0;\n\t"
        "tcgen05.mma.cta_group::1.kind::tf32 [%0], %1, %2, %3, {%4, %4, %4, %4}, p;\n\t}"
        :: "r"(d_tmem), "l"(a_desc), "l"(b_desc), "r"(idesc), "r"(0u), "r"(en)
        : "memory");
}
static constexpr uint64_t DESC_BASE_SW128 =
    (uint64_t(2) << 61) | (uint64_t(1) << 46) | (uint64_t(64) << 32) | (uint64_t(1) << 16);
#define MK_DESC(a) (DESC_BASE_SW128 | ((uint64_t)((a) >> 4) & 0x3FFF))
static constexpr uint32_t IDESC_TF32 =
    (1u << 4) | (2u << 7) | (2u << 10) | (16u << 17) | (8u << 24);
#endif  // __CUDA_ARCH_SPECIFIC__

__global__ void __launch_bounds__(128, 1) fused_mma_kernel(
    const float* __restrict__ xmask, const float* __restrict__ ymask) {
    extern __shared__ char smem[];
    int tid = threadIdx.x;
    int b = blockIdx.z;
    int p0 = blockIdx.y * 128;
    int s0 = blockIdx.x * 128;

#if defined(__CUDA_ARCH_SPECIFIC__)
    uint32_t sbase = smem_u32(smem);
    int wid = tid >> 5;

    const float* Pg = g_hy_r  + ((size_t)b * L + p0) * D;
    const float* Qg = g_predW + ((size_t)b * L + p0) * D;
    const float* Sg = g_hx_r  + ((size_t)b * L + s0) * D;
    float* s_ssq   = (float*)(smem + SM_SSQ);
    float* s_smask = (float*)(smem + SM_SMASK);

    // TMEM alloc (256 cols: cross @0, tr @128)
    if (wid == 0) { TC_ALLOC(sbase, 256); TC_RELINQ(); }
    // 4 single-use mbarriers, one per K-stage commit
    if (tid == 0) {
        MBAR_INIT(sbase + 8, 1);
        MBAR_INIT(sbase + 16, 1);
        MBAR_INIT(sbase + 24, 1);
        MBAR_INIT(sbase + 32, 1);
    }

    s_ssq[tid]   = g_src_sq[b * L + s0 + tid];
    s_smask[tid] = xmask[b * L + s0 + tid];
    load_chunk64(Pg, smem, SM_BUF + 0 * OP_BYTES, tid);
    load_chunk64(Qg, smem, SM_BUF + 1 * OP_BYTES, tid);
    load_chunk64(Sg, smem, SM_BUF + 2 * OP_BYTES, tid);
    FENCE_ASYNC();
    __syncthreads();

    uint32_t tmem;
    asm volatile("ld.shared.b32 %0, [%1];" : "=r"(tmem) : "r"(sbase));

    #pragma unroll 1
    for (int kc = 0; kc < 4; kc++) {
        int cur = kc & 1;
        uint32_t boff = SM_BUF + cur * STAGE_BYTES;
        if (wid == 0 && elect_one()) {
            uint64_t pa = MK_DESC(sbase + boff + 0 * OP_BYTES);
            uint64_t qa = MK_DESC(sbase + boff + 1 * OP_BYTES);
            uint64_t sd = MK_DESC(sbase + boff + 2 * OP_BYTES);
            #pragma unroll
            for (int g = 0; g < 2; g++)
                #pragma unroll
                for (int ks = 0; ks < 4; ks++) {
                    uint64_t o = (uint64_t)(g * 1024 + ks * 2);
                    uint32_t en = (kc | g | ks) ? 1u : 0u;
                    mma_tf32_ss(tmem + 0,   pa + o, sd + o, IDESC_TF32, en);
                    mma_tf32_ss(tmem + 128, qa + o, sd + o, IDESC_TF32, en);
                }
            TC_COMMIT(sbase + 8 + kc * 8);   // commit kc -> mbar[kc]
        }
        if (kc < 3) {
            // refill buffer cur^1, last used by commit kc-1 -> wait mbar[kc-1]
            if (kc >= 1) MBAR_WAIT0(sbase + 8 + (kc - 1) * 8);
            uint32_t noff = SM_BUF + (cur ^ 1) * STAGE_BYTES;
            int ko = (kc + 1) * 64;
            load_chunk64(Pg + ko, smem, noff + 0 * OP_BYTES, tid);
            load_chunk64(Qg + ko, smem, noff + 1 * OP_BYTES, tid);
            load_chunk64(Sg + ko, smem, noff + 2 * OP_BYTES, tid);
            FENCE_ASYNC();
        }
        __syncthreads();
    }
    // commit 3 tracks ALL prior MMAs -> one wait suffices
    MBAR_WAIT0(sbase + 8 + 3 * 8);
    TC_FENCE_AFTER();

    // epilogue: per-thread row, online softmax over 128 cols
    int row = tid;
    float psq = g_pred_sq[b * L + p0 + row];
    float pm  = ymask[b * L + p0 + row];
    float m = -INFINITY, Z = 0.f, Nv = 0.f;

    #pragma unroll 1
    for (int cc = 0; cc < 4; cc++) {
        uint32_t cx[32], tr[32];
        LDTM32(cx, tmem + 0   + cc * 32);
        LDTM32(tr, tmem + 128 + cc * 32);
        TC_WAIT_LD();
        #pragma unroll
        for (int j = 0; j < 32; j++) {
            int s = cc * 32 + j;
            float smv = s_smask[s];
            float cross = __uint_as_float(cx[j]);
            float tv = __uint_as_float(tr[j]);
            float t = (pm * smv != 0.f) ? tv : NEG_INF;
            float c = sqrtf(fmaxf(psq + s_ssq[s] - 2.f * cross, 0.f));
            if (t > m) {
                float sc = __expf(m - t);
                Z = Z * sc + 1.f;
                Nv = Nv * sc + c;
                m = t;
            } else {
                float e = __expf(t - m);
                Z += e;
                Nv += e * c;
            }
        }
    }
    int sidx = (b * 16 + blockIdx.x) * L + p0 + row;
    g_stat_m[sidx] = m;
    g_stat_z[sidx] = Z;
    g_stat_n[sidx] = Nv;

    __syncthreads();
    if (tid == 0) {
        MBAR_INVAL(sbase + 8);
        MBAR_INVAL(sbase + 16);
        MBAR_INVAL(sbase + 24);
        MBAR_INVAL(sbase + 32);
    }
    __syncthreads();
    if (wid == 0) TC_DEALLOC(tmem, 256);
#else
    // Generic-PTX fallback (never runs on GB300: driver picks sm_103a cubin).
    int row = tid;
    int p = p0 + row;
    const float* Pr = g_hy_r  + ((size_t)b * L + p) * D;
    const float* Qr = g_predW + ((size_t)b * L + p) * D;
    float psq = g_pred_sq[b * L + p];
    float pm  = ymask[b * L + p];
    float m = -INFINITY, Z = 0.f, Nv = 0.f;
    for (int s = 0; s < 128; s++) {
        const float* Sr = g_hx_r + ((size_t)b * L + s0 + s) * D;
        float cross = 0.f, tv = 0.f;
        for (int k = 0; k < D; k++) {
            cross += Pr[k] * Sr[k];
            tv += Qr[k] * Sr[k];
        }
        float smv = xmask[b * L + s0 + s];
        float t = (pm * smv != 0.f) ? tv : NEG_INF;
        float c = sqrtf(fmaxf(psq + g_src_sq[b * L + s0 + s] - 2.f * cross, 0.f));
        float mn = fmaxf(m, t);
        float sc = __expf(m - mn);
        float e = __expf(t - mn);
        Z = Z * sc + e;
        Nv = Nv * sc + e * c;
        m = mn;
    }
    int sidx = (b * 16 + blockIdx.x) * L + p0 + row;
    g_stat_m[sidx] = m;
    g_stat_z[sidx] = Z;
    g_stat_n[sidx] = Nv;
#endif
}

// ---------------- kernel 4: combine 16 s-tile stats per row ----------------
__global__ void combine_kernel() {
    int row = blockIdx.x * blockDim.x + threadIdx.x;
    if (row >= B * L) return;
    int b = row / L;
    int p = row % L;
    float m = -INFINITY, Z = 0.f, Nv = 0.f;
    #pragma unroll
    for (int st = 0; st < 16; st++) {
        int idx = (b * 16 + st) * L + p;
        float ms = g_stat_m[idx], zs = g_stat_z[idx], ns = g_stat_n[idx];
        float mn = fmaxf(m, ms);
        float s1 = __expf(m - mn);
        float s2 = __expf(ms - mn);
        Z = Z * s1 + zs * s2;
        Nv = Nv * s1 + ns * s2;
        m = mn;
    }
    g_rowval[row] = Nv / Z;
}

// ---------------- kernel 5: deterministic final reduction ----------------
__global__ void finalize_kernel(const float* __restrict__ xmask,
                                const float* __restrict__ ymask,
                                float* __restrict__ out) {
    __shared__ float red[256];
    __shared__ float inv[B];
    int tid = threadIdx.x;
    float s = 0.f;
    for (int i = tid; i < B * L; i += 256) s += g_rowval[i];
    red[tid] = s;
    __syncthreads();
    for (int o = 128; o > 0; o >>= 1) {
        if (tid < o) red[tid] += red[tid + o];
        __syncthreads();
    }
    if (tid < B) {
        float n1 = 0.f, n2 = 0.f;
        for (int i = 0; i < L; i++) {
            n1 += ymask[tid * L + i];
            n2 += xmask[tid * L + i];
        }
        inv[tid] = 1.f / (n1 * n2);
    }
    __syncthreads();
    if (tid == 0) {
        float F = 0.f;
        for (int bb = 0; bb < B; bb++) F += inv[bb];
        out[0] = red[0] * F / (float)(B * B);
    }
}

// ---------------- launch ----------------
extern "C" void kernel_launch(void* const* d_in, const int* in_sizes, int n_in,
                              void* d_out, int out_size) {
    const float* hx = (const float*)d_in[0];
    const float* hy = (const float*)d_in[1];
    const float* xm = (const float*)d_in[2];
    const float* ym = (const float*)d_in[3];
    const float* W  = (const float*)d_in[4];
    float* out = (float*)d_out;

    cudaFuncSetAttribute(fused_mma_kernel,
                         cudaFuncAttributeMaxDynamicSharedMemorySize, SMEM_TOTAL);

    sqnorms_round_kernel<<<(B * L * 32 + 255) / 256, 256>>>(hx, hy);
    predw_gemm_kernel<<<dim3(D / 64, (B * L) / 128), 256>>>(hy, W);
    fused_mma_kernel<<<dim3(L / 128, L / 128, B), 128, SMEM_TOTAL>>>(xm, ym);
    combine_kernel<<<(B * L + 255) / 256, 256>>>();
    finalize_kernel<<<1, 256>>>(xm, ym, out);
}

// round 4
// speedup vs baseline: 5.3331x; 2.2245x over previous
#include <cuda_runtime.h>
#include <cuda_bf16.h>
#include <math.h>
#include <cstdint>

#define B 8
#define L 2048
#define D 256
#define NEG_INF -1e10f

// ---------------- device scratch (static, no allocations) ----------------
__device__ __align__(16) uint32_t g_sx[B * L * D / 2];   // hx bf16x2 packed, row-major
__device__ __align__(16) uint32_t g_sy[B * L * D / 2];   // hy bf16x2
__device__ __align__(16) uint32_t g_wt[D * D / 2];       // W^T [n][k] bf16x2
__device__ __align__(16) uint32_t g_pw[B * L * D / 2];   // predW bf16x2
__device__ float g_pred_sq[B * L];
__device__ float g_src_sq[B * L];
__device__ float g_rowval[B * L];

// ---------------- generic helpers ----------------
__device__ __forceinline__ uint32_t smem_u32(const void* p) {
    uint32_t a;
    asm("{ .reg .u64 t; cvta.to.shared.u64 t, %1; cvt.u32.u64 %0, t; }" : "=r"(a) : "l"(p));
    return a;
}
__device__ __forceinline__ uint32_t pack_bf16x2(float lo, float hi) {
    uint32_t u;
    asm("cvt.rn.bf16x2.f32 %0, %1, %2;" : "=r"(u) : "f"(hi), "f"(lo));
    return u;
}
__device__ __forceinline__ float2 unpack_bf(uint32_t u) {
    __nv_bfloat162 h = *reinterpret_cast<__nv_bfloat162*>(&u);
    return make_float2(__bfloat162float(h.x), __bfloat162float(h.y));
}

// Load a [nrows x 256] bf16 tile (packed u32 rows of 128) into SW128 blocked-atom smem.
__device__ __forceinline__ void load_tile_bf16(const uint32_t* __restrict__ g,
                                               char* sm, uint32_t off,
                                               int tid, int nthr, int nrows) {
    const uint4* g4 = (const uint4*)g;
    int total = nrows * 32;            // uint4 per tile
    int ar = nrows >> 3;               // atom-rows
    for (int idx = tid; idx < total; idx += nthr) {
        uint4 v = __ldg(&g4[idx]);
        int r = idx >> 5;
        uint32_t kb = (uint32_t)(idx & 31) * 16u;
        uint32_t boff = (uint32_t)((r >> 3) + (int)(kb >> 7) * ar) * 1024u
                        + (uint32_t)(r & 7) * 128u + (kb & 127u);
        uint32_t sw = boff ^ ((boff >> 3) & 0x70);
        *(uint4*)(sm + off + sw) = v;
    }
}

// ---------------- kernel 1: prep — bf16 convert + fp32 sq-norms ----------------
__global__ void prep_kernel(const float* __restrict__ hx, const float* __restrict__ hy) {
    int gtid = blockIdx.x * blockDim.x + threadIdx.x;
    int row = gtid >> 5;
    int lane = gtid & 31;
    if (row >= B * L) return;
    const float2* xr = (const float2*)(hx + (size_t)row * D);
    const float2* yr = (const float2*)(hy + (size_t)row * D);
    uint32_t* xo = g_sx + (size_t)row * 128;
    uint32_t* yo = g_sy + (size_t)row * 128;
    float sx = 0.f, sy = 0.f;
    #pragma unroll
    for (int j = 0; j < 4; j++) {
        int c = j * 32 + lane;
        float2 vx = xr[c];
        sx += vx.x * vx.x + vx.y * vx.y;
        xo[c] = pack_bf16x2(vx.x, vx.y);
        float2 vy = yr[c];
        sy += vy.x * vy.x + vy.y * vy.y;
        yo[c] = pack_bf16x2(vy.x, vy.y);
    }
    #pragma unroll
    for (int o = 16; o > 0; o >>= 1) {
        sx += __shfl_down_sync(0xffffffffu, sx, o);
        sy += __shfl_down_sync(0xffffffffu, sy, o);
    }
    if (lane == 0) { g_src_sq[row] = sx; g_pred_sq[row] = sy; }
}

// ---------------- kernel 2: W transpose -> bf16 [n][k] ----------------
__global__ void wt_kernel(const float* __restrict__ W) {
    int n = blockIdx.x;          // 0..255
    int t = threadIdx.x;         // 0..127 (k pair)
    float a = W[(size_t)(2 * t) * D + n];
    float b = W[(size_t)(2 * t + 1) * D + n];
    g_wt[n * 128 + t] = pack_bf16x2(a, b);
}

// ---------------- tcgen05 machinery (sm_103a-only) ----------------
static constexpr uint64_t DESC_BASE_SW128 =
    (uint64_t(2) << 61) | (uint64_t(1) << 46) | (uint64_t(64) << 32) | (uint64_t(1) << 16);
#define MK_DESC(a) (DESC_BASE_SW128 | ((uint64_t)((a) >> 4) & 0x3FFF))
// bf16 idesc: dtype F32, atype/btype BF16, N=128, M=128
static constexpr uint32_t IDESC_BF16 =
    (1u << 4) | (1u << 7) | (1u << 10) | (16u << 17) | (8u << 24);

#if defined(__CUDA_ARCH_SPECIFIC__)
#define TC_ALLOC(sm, n)   asm volatile("tcgen05.alloc.cta_group::1.sync.aligned.shared::cta.b32 [%0], %1;" :: "r"(sm), "r"(n) : "memory")
#define TC_DEALLOC(t, n)  asm volatile("tcgen05.dealloc.cta_group::1.sync.aligned.b32 %0, %1;" :: "r"(t), "r"(n))
#define TC_RELINQ()       asm volatile("tcgen05.relinquish_alloc_permit.cta_group::1.sync.aligned;")
#define TC_COMMIT(mb)     asm volatile("tcgen05.commit.cta_group::1.mbarrier::arrive::one.shared::cluster.b64 [%0];" :: "r"(mb) : "memory")
#define TC_FENCE_AFTER()  asm volatile("tcgen05.fence::after_thread_sync;" ::: "memory")
#define TC_WAIT_LD()      asm volatile("tcgen05.wait::ld.sync.aligned;" ::: "memory")
#define MBAR_INIT(mb, c)  asm volatile("mbarrier.init.shared.b64 [%0], %1;" :: "r"(mb), "r"(c) : "memory")
#define MBAR_INVAL(mb)    asm volatile("mbarrier.inval.shared.b64 [%0];" :: "r"(mb) : "memory")
#define FENCE_ASYNC()     asm volatile("fence.proxy.async.shared::cta;" ::: "memory")

#define MBAR_WAIT(mb, par) do {                                                        \
    uint32_t _m = (mb), _p = (par), _d;                                                \
    asm volatile("{\n\t.reg .pred p;\n\t"                                              \
        "mbarrier.try_wait.parity.acquire.cta.shared::cta.b64 p, [%1], %2;\n\t"        \
        "selp.b32 %0, 1, 0, p;\n\t}" : "=r"(_d) : "r"(_m), "r"(_p) : "memory");        \
    if (!_d) {                                                                          \
        asm volatile("{\n\t.reg .pred P1;\n\tWL_%=:\n\t"                               \
            "mbarrier.try_wait.parity.acquire.cta.shared::cta.b64 P1, [%0], %1, 0x989680;\n\t" \
            "@P1 bra.uni WD_%=;\n\tbra.uni WL_%=;\n\tWD_%=:\n\t}"                      \
            :: "r"(_m), "r"(_p) : "memory");                                            \
    } } while (0)

#define LDTM32(r, addr)                                                                \
    asm volatile("tcgen05.ld.sync.aligned.32x32b.x32.b32 "                             \
        "{%0,%1,%2,%3,%4,%5,%6,%7,%8,%9,%10,%11,%12,%13,%14,%15,"                      \
        "%16,%17,%18,%19,%20,%21,%22,%23,%24,%25,%26,%27,%28,%29,%30,%31}, [%32];"     \
        : "=r"((r)[0]),"=r"((r)[1]),"=r"((r)[2]),"=r"((r)[3]),                          \
          "=r"((r)[4]),"=r"((r)[5]),"=r"((r)[6]),"=r"((r)[7]),                          \
          "=r"((r)[8]),"=r"((r)[9]),"=r"((r)[10]),"=r"((r)[11]),                        \
          "=r"((r)[12]),"=r"((r)[13]),"=r"((r)[14]),"=r"((r)[15]),                      \
          "=r"((r)[16]),"=r"((r)[17]),"=r"((r)[18]),"=r"((r)[19]),                      \
          "=r"((r)[20]),"=r"((r)[21]),"=r"((r)[22]),"=r"((r)[23]),                      \
          "=r"((r)[24]),"=r"((r)[25]),"=r"((r)[26]),"=r"((r)[27]),                      \
          "=r"((r)[28]),"=r"((r)[29]),"=r"((r)[30]),"=r"((r)[31])                       \
        : "r"(addr))

__device__ __forceinline__ uint32_t elect_one() {
    uint32_t pred;
    asm volatile("{\n\t.reg .pred p;\n\telect.sync _|p, 0xFFFFFFFF;\n\tselp.b32 %0, 1, 0, p;\n\t}" : "=r"(pred));
    return pred;
}
__device__ __forceinline__ void mma_bf16_ss(uint32_t d, uint64_t a, uint64_t b, uint32_t en) {
    asm volatile(
        "{\n\t.reg .pred p;\n\tsetp.ne.u32 p, %4, 0;\n\t"
        "tcgen05.mma.cta_group::1.kind::f16 [%0], %1, %2, %3, {%5,%5,%5,%5}, p;\n\t}"
        :: "r"(d), "l"(a), "l"(b), "r"(IDESC_BF16), "r"(en), "r"(0u)
        : "memory");
}
#endif  // __CUDA_ARCH_SPECIFIC__

// ---------------- kernel 3: predW via tcgen05 ----------------
// per CTA: rows m0..m0+127 ; D[128,256] = hy_bf16[128,256] @ Wt^T
#define PW_A   0u
#define PW_WT  65536u
#define PW_PTR 196608u
#define PW_MB  196624u
#define PW_SMEM 196640

__global__ void __launch_bounds__(128, 1) predw_kernel() {
    extern __shared__ char smem[];
    int tid = threadIdx.x;
    int m0 = blockIdx.x * 128;
#if defined(__CUDA_ARCH_SPECIFIC__)
    uint32_t sbase = smem_u32(smem);
    int wid = tid >> 5;
    if (wid == 0) { TC_ALLOC(sbase + PW_PTR, 256); TC_RELINQ(); }
    if (tid == 0) MBAR_INIT(sbase + PW_MB, 1);

    load_tile_bf16(g_sy + (size_t)m0 * 128, smem, PW_A, tid, 128, 128);
    load_tile_bf16(g_wt, smem, PW_WT, tid, 128, 256);
    FENCE_ASYNC();
    __syncthreads();

    uint32_t tmem;
    asm volatile("ld.shared.b32 %0, [%1];" : "=r"(tmem) : "r"(sbase + PW_PTR));

    if (wid == 0 && elect_one()) {
        uint64_t ad = MK_DESC(sbase + PW_A);
        uint64_t bd = MK_DESC(sbase + PW_WT);
        #pragma unroll
        for (int ks = 0; ks < 16; ks++) {
            uint64_t oa = (uint64_t)((ks >> 2) * 1024 + (ks & 3) * 2);
            uint64_t ob = (uint64_t)((ks >> 2) * 2048 + (ks & 3) * 2);
            uint32_t en = ks > 0 ? 1u : 0u;
            mma_bf16_ss(tmem + 0,   ad + oa, bd + ob,        en);
            mma_bf16_ss(tmem + 128, ad + oa, bd + ob + 1024, en);
        }
        TC_COMMIT(sbase + PW_MB);
    }
    __syncthreads();
    MBAR_WAIT(sbase + PW_MB, 0u);
    TC_FENCE_AFTER();

    // epilogue: 256 cols -> bf16x2 staged in smem (stride 132 to dodge banks), then coalesced store
    uint32_t* stage = (uint32_t*)smem;
    #pragma unroll 1
    for (int cb = 0; cb < 8; cb++) {
        uint32_t r[32];
        LDTM32(r, tmem + cb * 32);
        TC_WAIT_LD();
        #pragma unroll
        for (int j = 0; j < 16; j++)
            stage[tid * 132 + cb * 16 + j] =
                pack_bf16x2(__uint_as_float(r[2 * j]), __uint_as_float(r[2 * j + 1]));
    }
    __syncthreads();
    uint32_t* gout = g_pw + (size_t)m0 * 128;
    #pragma unroll 8
    for (int i = 0; i < 128; i++) {
        int idx = tid + i * 128;
        gout[idx] = stage[(idx >> 7) * 132 + (idx & 127)];
    }
    __syncthreads();
    if (tid == 0) MBAR_INVAL(sbase + PW_MB);
    __syncthreads();
    if (wid == 0) TC_DEALLOC(tmem, 256);
#else
    // dead generic-PTX fallback
    for (int n = tid; n < D; n += 128) {
        int row = m0;  // minimal valid work (never executed on GB300)
        float2 a0 = unpack_bf(g_sy[(size_t)row * 128]);
        float2 w0 = unpack_bf(g_wt[n * 128]);
        g_pw[(size_t)row * 128 + n / 2] = pack_bf16x2(a0.x * w0.x, a0.y * w0.y);
    }
#endif
}

// ---------------- kernel 4: fused dual-GEMM + full-row flash softmax --------
#define F_P    0u
#define F_Q    65536u
#define F_S    131072u
#define F_PTR  196608u
#define F_MB   196624u   // 2 mbars
#define F_SSQ  196640u   // [2][128] f32
#define F_SMK  197664u   // [2][128] f32
#define F_CMB  198688u   // 3 * 256 f32
#define F_SMEM 201760

__global__ void __launch_bounds__(256, 1) fused_kernel(
    const float* __restrict__ xmask, const float* __restrict__ ymask) {
    extern __shared__ char smem[];
    int tid = threadIdx.x;
    int b = blockIdx.x >> 4;
    int p0 = (blockIdx.x & 15) * 128;
#if defined(__CUDA_ARCH_SPECIFIC__)
    uint32_t sbase = smem_u32(smem);
    int wid = tid >> 5;

    if (wid == 0) { TC_ALLOC(sbase + F_PTR, 512); TC_RELINQ(); }
    if (tid == 0) { MBAR_INIT(sbase + F_MB, 1); MBAR_INIT(sbase + F_MB + 8, 1); }

    load_tile_bf16(g_sy + ((size_t)b * L + p0) * 128, smem, F_P, tid, 256, 128);
    load_tile_bf16(g_pw + ((size_t)b * L + p0) * 128, smem, F_Q, tid, 256, 128);
    load_tile_bf16(g_sx + ((size_t)b * L) * 128, smem, F_S, tid, 256, 128);
    float* ssq = (float*)(smem + F_SSQ);
    float* smk = (float*)(smem + F_SMK);
    if (tid < 128) {
        ssq[tid] = g_src_sq[b * L + tid];
        smk[tid] = xmask[b * L + tid];
    }
    FENCE_ASYNC();
    __syncthreads();

    uint32_t tmem;
    asm volatile("ld.shared.b32 %0, [%1];" : "=r"(tmem) : "r"(sbase + F_PTR));

    int row = tid & 127;
    int half = tid >> 7;
    float psq = g_pred_sq[b * L + p0 + row];
    float pm  = ymask[b * L + p0 + row];
    float m = -INFINITY, Z = 0.f, Nv = 0.f;

    uint64_t pd = MK_DESC(sbase + F_P);
    uint64_t qd = MK_DESC(sbase + F_Q);
    uint64_t sd = MK_DESC(sbase + F_S);

    // issue MMA_0 into buf0
    if (wid == 0 && elect_one()) {
        #pragma unroll
        for (int ks = 0; ks < 16; ks++) {
            uint64_t o = (uint64_t)((ks >> 2) * 1024 + (ks & 3) * 2);
            uint32_t en = ks > 0 ? 1u : 0u;
            mma_bf16_ss(tmem + 0,   pd + o, sd + o, en);
            mma_bf16_ss(tmem + 128, qd + o, sd + o, en);
        }
        TC_COMMIT(sbase + F_MB);
    }

    #pragma unroll 1
    for (int i = 0; i < 16; i++) {
        MBAR_WAIT(sbase + F_MB + (uint32_t)(i & 1) * 8, (uint32_t)((i >> 1) & 1));
        TC_FENCE_AFTER();
        if (i < 15) {
            load_tile_bf16(g_sx + ((size_t)b * L + (i + 1) * 128) * 128, smem, F_S, tid, 256, 128);
            if (tid < 128) {
                ssq[((i + 1) & 1) * 128 + tid] = g_src_sq[b * L + (i + 1) * 128 + tid];
                smk[((i + 1) & 1) * 128 + tid] = xmask[b * L + (i + 1) * 128 + tid];
            }
            FENCE_ASYNC();
        }
        __syncthreads();
        if (i < 15 && wid == 0 && elect_one()) {
            uint32_t dbase = tmem + (uint32_t)((i + 1) & 1) * 256;
            #pragma unroll
            for (int ks = 0; ks < 16; ks++) {
                uint64_t o = (uint64_t)((ks >> 2) * 1024 + (ks & 3) * 2);
                uint32_t en = ks > 0 ? 1u : 0u;
                mma_bf16_ss(dbase + 0,   pd + o, sd + o, en);
                mma_bf16_ss(dbase + 128, qd + o, sd + o, en);
            }
            TC_COMMIT(sbase + F_MB + (uint32_t)((i + 1) & 1) * 8);
        }
        // epilogue of iter i from buf i&1 (overlaps MMA_{i+1})
        uint32_t bufc = tmem + (uint32_t)(i & 1) * 256;
        float* ssq_s = ssq + (i & 1) * 128;
        float* smk_s = smk + (i & 1) * 128;
        #pragma unroll 1
        for (int ch = 0; ch < 2; ch++) {
            uint32_t colb = (uint32_t)(half * 64 + ch * 32);
            uint32_t cx[32], tr[32];
            LDTM32(cx, bufc + colb);
            LDTM32(tr, bufc + 128 + colb);
            TC_WAIT_LD();
            #pragma unroll
            for (int j = 0; j < 32; j++) {
                int s = (int)colb + j;
                float t = (pm * smk_s[s] != 0.f) ? __uint_as_float(tr[j]) : NEG_INF;
                float c = sqrtf(fmaxf(psq + ssq_s[s] - 2.f * __uint_as_float(cx[j]), 0.f));
                float mn = fmaxf(m, t);
                float sc = __expf(m - mn);
                float e  = __expf(t - mn);
                Z  = Z * sc + e;
                Nv = Nv * sc + e * c;
                m = mn;
            }
        }
        __syncthreads();
    }

    // combine halves (tid <-> tid+128), write rowval
    float* cm = (float*)(smem + F_CMB);
    cm[tid] = m; cm[256 + tid] = Z; cm[512 + tid] = Nv;
    __syncthreads();
    if (tid < 128) {
        float m2 = cm[tid + 128], z2 = cm[256 + tid + 128], n2 = cm[512 + tid + 128];
        float mn = fmaxf(m, m2);
        float s1 = __expf(m - mn);
        float s2 = __expf(m2 - mn);
        float Zt = Z * s1 + z2 * s2;
        float Nt = Nv * s1 + n2 * s2;
        g_rowval[b * L + p0 + tid] = Nt / Zt;
    }
    __syncthreads();
    if (tid == 0) { MBAR_INVAL(sbase + F_MB); MBAR_INVAL(sbase + F_MB + 8); }
    __syncthreads();
    if (wid == 0) TC_DEALLOC(tmem, 512);
#else
    // dead generic-PTX fallback (GB300 always loads the sm_103a cubin)
    if (tid < 128) {
        int p = p0 + tid;
        float psq = g_pred_sq[b * L + p];
        float pm  = ymask[b * L + p];
        float m = -INFINITY, Z = 0.f, Nv = 0.f;
        for (int s = 0; s < L; s++) {
            float cross = 0.f, tv = 0.f;
            for (int kk = 0; kk < 128; kk++) {
                float2 a = unpack_bf(g_sy[((size_t)b * L + p) * 128 + kk]);
                float2 q = unpack_bf(g_pw[((size_t)b * L + p) * 128 + kk]);
                float2 s2 = unpack_bf(g_sx[((size_t)b * L + s) * 128 + kk]);
                cross += a.x * s2.x + a.y * s2.y;
                tv += q.x * s2.x + q.y * s2.y;
            }
            float t = (pm * xmask[b * L + s] != 0.f) ? tv : NEG_INF;
            float c = sqrtf(fmaxf(psq + g_src_sq[b * L + s] - 2.f * cross, 0.f));
            float mn = fmaxf(m, t);
            float sc = __expf(m - mn);
            float e = __expf(t - mn);
            Z = Z * sc + e;
            Nv = Nv * sc + e * c;
            m = mn;
        }
        g_rowval[b * L + p] = Nv / Z;
    }
#endif
}

// ---------------- kernel 5: deterministic final reduction ----------------
__global__ void finalize_kernel(const float* __restrict__ xmask,
                                const float* __restrict__ ymask,
                                float* __restrict__ out) {
    __shared__ float red[256];
    __shared__ float inv[B];
    int tid = threadIdx.x;
    float s = 0.f;
    for (int i = tid; i < B * L; i += 256) s += g_rowval[i];
    red[tid] = s;
    __syncthreads();
    for (int o = 128; o > 0; o >>= 1) {
        if (tid < o) red[tid] += red[tid + o];
        __syncthreads();
    }
    if (tid < B) {
        float n1 = 0.f, n2 = 0.f;
        for (int i = 0; i < L; i++) {
            n1 += ymask[tid * L + i];
            n2 += xmask[tid * L + i];
        }
        inv[tid] = 1.f / (n1 * n2);
    }
    __syncthreads();
    if (tid == 0) {
        float F = 0.f;
        for (int bb = 0; bb < B; bb++) F += inv[bb];
        out[0] = red[0] * F / (float)(B * B);
    }
}

// ---------------- launch ----------------
extern "C" void kernel_launch(void* const* d_in, const int* in_sizes, int n_in,
                              void* d_out, int out_size) {
    const float* hx = (const float*)d_in[0];
    const float* hy = (const float*)d_in[1];
    const float* xm = (const float*)d_in[2];
    const float* ym = (const float*)d_in[3];
    const float* W  = (const float*)d_in[4];
    float* out = (float*)d_out;

    cudaFuncSetAttribute(predw_kernel,
                         cudaFuncAttributeMaxDynamicSharedMemorySize, PW_SMEM);
    cudaFuncSetAttribute(fused_kernel,
                         cudaFuncAttributeMaxDynamicSharedMemorySize, F_SMEM);

    prep_kernel<<<(B * L * 32 + 255) / 256, 256>>>(hx, hy);
    wt_kernel<<<D, 128>>>(W);
    predw_kernel<<<(B * L) / 128, 128, PW_SMEM>>>();
    fused_kernel<<<B * (L / 128), 256, F_SMEM>>>(xm, ym);
    finalize_kernel<<<1, 256>>>(xm, ym, out);
}

// round 5
// speedup vs baseline: 8.8813x; 1.6653x over previous
#include <cuda_runtime.h>
#include <cuda_bf16.h>
#include <math.h>
#include <cstdint>

#define B 8
#define L 2048
#define D 256
#define NEG_INF -1e10f

// ---------------- device scratch (static, no allocations) ----------------
__device__ __align__(16) uint32_t g_sx[B * L * D / 2];   // hx bf16x2 packed, row-major
__device__ __align__(16) uint32_t g_sy[B * L * D / 2];   // hy bf16x2
__device__ __align__(16) uint32_t g_wt[D * D / 2];       // W^T [n][k] bf16x2
__device__ __align__(16) uint32_t g_pw[B * L * D / 2];   // predW bf16x2
__device__ float g_pred_sq[B * L];
__device__ float g_src_sq[B * L];
__device__ float g_rowval[B * L];

// ---------------- generic helpers ----------------
__device__ __forceinline__ uint32_t smem_u32(const void* p) {
    uint32_t a;
    asm("{ .reg .u64 t; cvta.to.shared.u64 t, %1; cvt.u32.u64 %0, t; }" : "=r"(a) : "l"(p));
    return a;
}
__device__ __forceinline__ uint32_t pack_bf16x2(float lo, float hi) {
    uint32_t u;
    asm("cvt.rn.bf16x2.f32 %0, %1, %2;" : "=r"(u) : "f"(hi), "f"(lo));
    return u;
}
__device__ __forceinline__ float2 unpack_bf(uint32_t u) {
    __nv_bfloat162 h = *reinterpret_cast<__nv_bfloat162*>(&u);
    return make_float2(__bfloat162float(h.x), __bfloat162float(h.y));
}
__device__ __forceinline__ float sqrt_fast(float v) {
    float r;
    asm("sqrt.approx.f32 %0, %1;" : "=f"(r) : "f"(v));
    return r;
}

// Load a [nrows x 256] bf16 tile (packed u32 rows of 128) into SW128 blocked-atom smem.
__device__ __forceinline__ void load_tile_bf16(const uint32_t* __restrict__ g,
                                               char* sm, uint32_t off,
                                               int tid, int nthr, int nrows) {
    const uint4* g4 = (const uint4*)g;
    int total = nrows * 32;            // uint4 per tile
    int ar = nrows >> 3;               // atom-rows
    for (int idx = tid; idx < total; idx += nthr) {
        uint4 v = __ldg(&g4[idx]);
        int r = idx >> 5;
        uint32_t kb = (uint32_t)(idx & 31) * 16u;
        uint32_t boff = (uint32_t)((r >> 3) + (int)(kb >> 7) * ar) * 1024u
                        + (uint32_t)(r & 7) * 128u + (kb & 127u);
        uint32_t sw = boff ^ ((boff >> 3) & 0x70);
        *(uint4*)(sm + off + sw) = v;
    }
}

// ---------------- kernel 1: prep — bf16 convert + fp32 sq-norms ----------------
__global__ void prep_kernel(const float* __restrict__ hx, const float* __restrict__ hy) {
    int gtid = blockIdx.x * blockDim.x + threadIdx.x;
    int row = gtid >> 5;
    int lane = gtid & 31;
    if (row >= B * L) return;
    const float2* xr = (const float2*)(hx + (size_t)row * D);
    const float2* yr = (const float2*)(hy + (size_t)row * D);
    uint32_t* xo = g_sx + (size_t)row * 128;
    uint32_t* yo = g_sy + (size_t)row * 128;
    float sx = 0.f, sy = 0.f;
    #pragma unroll
    for (int j = 0; j < 4; j++) {
        int c = j * 32 + lane;
        float2 vx = xr[c];
        sx += vx.x * vx.x + vx.y * vx.y;
        xo[c] = pack_bf16x2(vx.x, vx.y);
        float2 vy = yr[c];
        sy += vy.x * vy.x + vy.y * vy.y;
        yo[c] = pack_bf16x2(vy.x, vy.y);
    }
    #pragma unroll
    for (int o = 16; o > 0; o >>= 1) {
        sx += __shfl_down_sync(0xffffffffu, sx, o);
        sy += __shfl_down_sync(0xffffffffu, sy, o);
    }
    if (lane == 0) { g_src_sq[row] = sx; g_pred_sq[row] = sy; }
}

// ---------------- kernel 2: W transpose -> bf16 [n][k] ----------------
__global__ void wt_kernel(const float* __restrict__ W) {
    int n = blockIdx.x;          // 0..255
    int t = threadIdx.x;         // 0..127 (k pair)
    float a = W[(size_t)(2 * t) * D + n];
    float b = W[(size_t)(2 * t + 1) * D + n];
    g_wt[n * 128 + t] = pack_bf16x2(a, b);
}

// ---------------- tcgen05 machinery (sm_103a-only) ----------------
static constexpr uint64_t DESC_BASE_SW128 =
    (uint64_t(2) << 61) | (uint64_t(1) << 46) | (uint64_t(64) << 32) | (uint64_t(1) << 16);
#define MK_DESC(a) (DESC_BASE_SW128 | ((uint64_t)((a) >> 4) & 0x3FFF))
// bf16 idesc: dtype F32, atype/btype BF16
static constexpr uint32_t IDESC_BF16_N128 =
    (1u << 4) | (1u << 7) | (1u << 10) | (16u << 17) | (8u << 24);
static constexpr uint32_t IDESC_BF16_N64 =
    (1u << 4) | (1u << 7) | (1u << 10) | (8u << 17) | (8u << 24);

#if defined(__CUDA_ARCH_SPECIFIC__)
#define TC_ALLOC(sm, n)   asm volatile("tcgen05.alloc.cta_group::1.sync.aligned.shared::cta.b32 [%0], %1;" :: "r"(sm), "r"(n) : "memory")
#define TC_DEALLOC(t, n)  asm volatile("tcgen05.dealloc.cta_group::1.sync.aligned.b32 %0, %1;" :: "r"(t), "r"(n))
#define TC_RELINQ()       asm volatile("tcgen05.relinquish_alloc_permit.cta_group::1.sync.aligned;")
#define TC_COMMIT(mb)     asm volatile("tcgen05.commit.cta_group::1.mbarrier::arrive::one.shared::cluster.b64 [%0];" :: "r"(mb) : "memory")
#define TC_FENCE_AFTER()  asm volatile("tcgen05.fence::after_thread_sync;" ::: "memory")
#define TC_WAIT_LD()      asm volatile("tcgen05.wait::ld.sync.aligned;" ::: "memory")
#define MBAR_INIT(mb, c)  asm volatile("mbarrier.init.shared.b64 [%0], %1;" :: "r"(mb), "r"(c) : "memory")
#define MBAR_INVAL(mb)    asm volatile("mbarrier.inval.shared.b64 [%0];" :: "r"(mb) : "memory")
#define MBAR_ARRIVE(mb)   asm volatile("mbarrier.arrive.shared.b64 _, [%0];" :: "r"(mb) : "memory")
#define FENCE_ASYNC()     asm volatile("fence.proxy.async.shared::cta;" ::: "memory")

#define MBAR_WAIT(mb, par) do {                                                        \
    uint32_t _m = (mb), _p = (par), _d;                                                \
    asm volatile("{\n\t.reg .pred p;\n\t"                                              \
        "mbarrier.try_wait.parity.acquire.cta.shared::cta.b64 p, [%1], %2;\n\t"        \
        "selp.b32 %0, 1, 0, p;\n\t}" : "=r"(_d) : "r"(_m), "r"(_p) : "memory");        \
    if (!_d) {                                                                          \
        asm volatile("{\n\t.reg .pred P1;\n\tWL_%=:\n\t"                               \
            "mbarrier.try_wait.parity.acquire.cta.shared::cta.b64 P1, [%0], %1, 0x989680;\n\t" \
            "@P1 bra.uni WD_%=;\n\tbra.uni WL_%=;\n\tWD_%=:\n\t}"                      \
            :: "r"(_m), "r"(_p) : "memory");                                            \
    } } while (0)

#define LDTM32(r, addr)                                                                \
    asm volatile("tcgen05.ld.sync.aligned.32x32b.x32.b32 "                             \
        "{%0,%1,%2,%3,%4,%5,%6,%7,%8,%9,%10,%11,%12,%13,%14,%15,"                      \
        "%16,%17,%18,%19,%20,%21,%22,%23,%24,%25,%26,%27,%28,%29,%30,%31}, [%32];"     \
        : "=r"((r)[0]),"=r"((r)[1]),"=r"((r)[2]),"=r"((r)[3]),                          \
          "=r"((r)[4]),"=r"((r)[5]),"=r"((r)[6]),"=r"((r)[7]),                          \
          "=r"((r)[8]),"=r"((r)[9]),"=r"((r)[10]),"=r"((r)[11]),                        \
          "=r"((r)[12]),"=r"((r)[13]),"=r"((r)[14]),"=r"((r)[15]),                      \
          "=r"((r)[16]),"=r"((r)[17]),"=r"((r)[18]),"=r"((r)[19]),                      \
          "=r"((r)[20]),"=r"((r)[21]),"=r"((r)[22]),"=r"((r)[23]),                      \
          "=r"((r)[24]),"=r"((r)[25]),"=r"((r)[26]),"=r"((r)[27]),                      \
          "=r"((r)[28]),"=r"((r)[29]),"=r"((r)[30]),"=r"((r)[31])                       \
        : "r"(addr))

__device__ __forceinline__ uint32_t elect_one() {
    uint32_t pred;
    asm volatile("{\n\t.reg .pred p;\n\telect.sync _|p, 0xFFFFFFFF;\n\tselp.b32 %0, 1, 0, p;\n\t}" : "=r"(pred));
    return pred;
}
__device__ __forceinline__ void mma_bf16_n128(uint32_t d, uint64_t a, uint64_t b, uint32_t en) {
    asm volatile(
        "{\n\t.reg .pred p;\n\tsetp.ne.u32 p, %4, 0;\n\t"
        "tcgen05.mma.cta_group::1.kind::f16 [%0], %1, %2, %3, {%5,%5,%5,%5}, p;\n\t}"
        :: "r"(d), "l"(a), "l"(b), "r"(IDESC_BF16_N128), "r"(en), "r"(0u)
        : "memory");
}
__device__ __forceinline__ void mma_bf16_n64(uint32_t d, uint64_t a, uint64_t b, uint32_t en) {
    asm volatile(
        "{\n\t.reg .pred p;\n\tsetp.ne.u32 p, %4, 0;\n\t"
        "tcgen05.mma.cta_group::1.kind::f16 [%0], %1, %2, %3, {%5,%5,%5,%5}, p;\n\t}"
        :: "r"(d), "l"(a), "l"(b), "r"(IDESC_BF16_N64), "r"(en), "r"(0u)
        : "memory");
}
#endif  // __CUDA_ARCH_SPECIFIC__

// ---------------- kernel 3: predW via tcgen05 ----------------
#define PW_A   0u
#define PW_WT  65536u
#define PW_PTR 196608u
#define PW_MB  196624u
#define PW_SMEM 196640

__global__ void __launch_bounds__(128, 1) predw_kernel() {
    extern __shared__ char smem[];
    int tid = threadIdx.x;
    int m0 = blockIdx.x * 128;
#if defined(__CUDA_ARCH_SPECIFIC__)
    uint32_t sbase = smem_u32(smem);
    int wid = tid >> 5;
    if (wid == 0) { TC_ALLOC(sbase + PW_PTR, 256); TC_RELINQ(); }
    if (tid == 0) MBAR_INIT(sbase + PW_MB, 1);

    load_tile_bf16(g_sy + (size_t)m0 * 128, smem, PW_A, tid, 128, 128);
    load_tile_bf16(g_wt, smem, PW_WT, tid, 128, 256);
    FENCE_ASYNC();
    __syncthreads();

    uint32_t tmem;
    asm volatile("ld.shared.b32 %0, [%1];" : "=r"(tmem) : "r"(sbase + PW_PTR));

    if (wid == 0 && elect_one()) {
        uint64_t ad = MK_DESC(sbase + PW_A);
        uint64_t bd = MK_DESC(sbase + PW_WT);
        #pragma unroll
        for (int ks = 0; ks < 16; ks++) {
            uint64_t oa = (uint64_t)((ks >> 2) * 1024 + (ks & 3) * 2);
            uint64_t ob = (uint64_t)((ks >> 2) * 2048 + (ks & 3) * 2);
            uint32_t en = ks > 0 ? 1u : 0u;
            mma_bf16_n128(tmem + 0,   ad + oa, bd + ob,        en);
            mma_bf16_n128(tmem + 128, ad + oa, bd + ob + 1024, en);
        }
        TC_COMMIT(sbase + PW_MB);
    }
    __syncthreads();
    MBAR_WAIT(sbase + PW_MB, 0u);
    TC_FENCE_AFTER();

    uint32_t* stage = (uint32_t*)smem;
    #pragma unroll 1
    for (int cb = 0; cb < 8; cb++) {
        uint32_t r[32];
        LDTM32(r, tmem + cb * 32);
        TC_WAIT_LD();
        #pragma unroll
        for (int j = 0; j < 16; j++)
            stage[tid * 132 + cb * 16 + j] =
                pack_bf16x2(__uint_as_float(r[2 * j]), __uint_as_float(r[2 * j + 1]));
    }
    __syncthreads();
    uint32_t* gout = g_pw + (size_t)m0 * 128;
    #pragma unroll 8
    for (int i = 0; i < 128; i++) {
        int idx = tid + i * 128;
        gout[idx] = stage[(idx >> 7) * 132 + (idx & 127)];
    }
    __syncthreads();
    if (tid == 0) MBAR_INVAL(sbase + PW_MB);
    __syncthreads();
    if (wid == 0) TC_DEALLOC(tmem, 256);
#else
    for (int n = tid; n < D; n += 128) {
        int row = m0;
        float2 a0 = unpack_bf(g_sy[(size_t)row * 128]);
        float2 w0 = unpack_bf(g_wt[n * 128]);
        g_pw[(size_t)row * 128 + n / 2] = pack_bf16x2(a0.x * w0.x, a0.y * w0.y);
    }
#endif
}

// ---------------- kernel 4: warp-specialized fused dual-GEMM + flash softmax --
// 384 threads: warps 0-7 consumers (epilogue), warps 8-11 producers (S loads + MMA).
// TMEM: 4 buffers x 128 cols (cross@+0 N=64, tr@+64). S smem double buffered.
#define F_P     0u
#define F_Q     65536u
#define F_S     131072u      // 2 x 32768
#define F_SSQ   196608u      // 2048 f32
#define F_SMK   204800u      // 2048 f32
#define F_FLAG  212992u      // 32 f32 tile flags
#define F_PTR   213120u
#define F_MBF   213136u      // full[4]
#define F_MBE   213168u      // empty[4]
#define F_CMB   213200u      // 3*256 f32
#define F_SMEM  216320

__global__ void __launch_bounds__(384, 1) fused_kernel(
    const float* __restrict__ xmask, const float* __restrict__ ymask) {
    extern __shared__ char smem[];
    int tid = threadIdx.x;
    int b = blockIdx.x >> 4;
    int p0 = (blockIdx.x & 15) * 128;
#if defined(__CUDA_ARCH_SPECIFIC__)
    uint32_t sbase = smem_u32(smem);
    int wid = tid >> 5;
    int lane = tid & 31;

    if (wid == 0) { TC_ALLOC(sbase + F_PTR, 512); TC_RELINQ(); }
    if (tid == 0) {
        #pragma unroll
        for (int k = 0; k < 4; k++) {
            MBAR_INIT(sbase + F_MBF + k * 8, 1);     // full: 1 commit
            MBAR_INIT(sbase + F_MBE + k * 8, 256);   // empty: 256 consumer arrivals
        }
    }

    // prologue: P, Q, ssq, smask loaded by all 384 threads
    load_tile_bf16(g_sy + ((size_t)b * L + p0) * 128, smem, F_P, tid, 384, 128);
    load_tile_bf16(g_pw + ((size_t)b * L + p0) * 128, smem, F_Q, tid, 384, 128);
    float* s_ssq  = (float*)(smem + F_SSQ);
    float* s_smk  = (float*)(smem + F_SMK);
    float* s_flag = (float*)(smem + F_FLAG);
    for (int i = tid; i < L; i += 384) {
        s_ssq[i] = g_src_sq[b * L + i];
        s_smk[i] = xmask[b * L + i];
    }
    FENCE_ASYNC();
    __syncthreads();
    if (tid < 32) {           // per-64 s-tile "has any valid" flags
        float f = 0.f;
        #pragma unroll 8
        for (int i = 0; i < 64; i++) f = fmaxf(f, s_smk[tid * 64 + i]);
        s_flag[tid] = f;
    }
    __syncthreads();

    uint32_t tmem;
    asm volatile("ld.shared.b32 %0, [%1];" : "=r"(tmem) : "r"(sbase + F_PTR));

    if (tid < 256) {
        // ---------------- consumers ----------------
        int sp = wid & 3;
        int half = wid >> 2;
        int row = sp * 32 + lane;
        float psq = g_pred_sq[b * L + p0 + row];
        float pm  = ymask[b * L + p0 + row];
        float m = -INFINITY, Z = 0.f, Nv = 0.f;

        #pragma unroll 1
        for (int j = 0; j < 32; j++) {
            MBAR_WAIT(sbase + F_MBF + (uint32_t)(j & 3) * 8, (uint32_t)((j >> 2) & 1));
            TC_FENCE_AFTER();
            unsigned okrow = __all_sync(0xffffffffu, (pm != 0.f) && (m > -1e9f));
            if (!(okrow && s_flag[j] == 0.f)) {
                uint32_t bufc = tmem + (uint32_t)(j & 3) * 128u;
                uint32_t cxr[32], trr[32];
                LDTM32(cxr, bufc + (uint32_t)(half * 32));
                LDTM32(trr, bufc + 64u + (uint32_t)(half * 32));
                TC_WAIT_LD();
                int sb0 = j * 64 + half * 32;
                float tv[32], cv[32];
                #pragma unroll
                for (int jj = 0; jj < 32; jj++) {
                    int s = sb0 + jj;
                    float cross = __uint_as_float(cxr[jj]);
                    float d2 = fmaxf(fmaf(-2.f, cross, psq + s_ssq[s]), 0.f);
                    cv[jj] = sqrt_fast(d2);
                    tv[jj] = (pm * s_smk[s] != 0.f) ? __uint_as_float(trr[jj]) : NEG_INF;
                }
                float mx[16];
                #pragma unroll
                for (int jj = 0; jj < 16; jj++) mx[jj] = fmaxf(tv[jj], tv[jj + 16]);
                #pragma unroll
                for (int o = 8; o >= 1; o >>= 1)
                    #pragma unroll
                    for (int jj = 0; jj < o; jj++) mx[jj] = fmaxf(mx[jj], mx[jj + o]);
                float mn = fmaxf(m, mx[0]);
                float sc = __expf(m - mn);
                Z *= sc; Nv *= sc; m = mn;
                float za[4] = {0.f, 0.f, 0.f, 0.f}, na[4] = {0.f, 0.f, 0.f, 0.f};
                #pragma unroll
                for (int jj = 0; jj < 32; jj++) {
                    float e = __expf(tv[jj] - mn);
                    za[jj & 3] += e;
                    na[jj & 3] = fmaf(e, cv[jj], na[jj & 3]);
                }
                Z  += (za[0] + za[1]) + (za[2] + za[3]);
                Nv += (na[0] + na[1]) + (na[2] + na[3]);
            }
            MBAR_ARRIVE(sbase + F_MBE + (uint32_t)(j & 3) * 8);
        }
        float* cm = (float*)(smem + F_CMB);
        cm[tid] = m; cm[256 + tid] = Z; cm[512 + tid] = Nv;
    } else {
        // ---------------- producers ----------------
        int ptid = tid - 256;
        uint64_t pd = MK_DESC(sbase + F_P);
        uint64_t qd = MK_DESC(sbase + F_Q);
        #pragma unroll 1
        for (int j = 0; j < 32; j++) {
            if (j >= 2)  // smem buf (j&1) free once MMA_{j-2} completed
                MBAR_WAIT(sbase + F_MBF + (uint32_t)((j - 2) & 3) * 8,
                          (uint32_t)(((j - 2) >> 2) & 1));
            load_tile_bf16(g_sx + ((size_t)b * L + j * 64) * 128, smem,
                           F_S + (uint32_t)(j & 1) * 32768u, ptid, 128, 64);
            FENCE_ASYNC();
            asm volatile("bar.sync 1, 128;" ::: "memory");
            if (wid == 8) {
                if (j >= 4)  // TMEM buf (j&3) free once consumers drained j-4
                    MBAR_WAIT(sbase + F_MBE + (uint32_t)(j & 3) * 8,
                              (uint32_t)(((j >> 2) - 1) & 1));
                if (elect_one()) {
                    uint64_t sd = MK_DESC(sbase + F_S + (uint32_t)(j & 1) * 32768u);
                    uint32_t dbase = tmem + (uint32_t)(j & 3) * 128u;
                    #pragma unroll
                    for (int ks = 0; ks < 16; ks++) {
                        uint64_t oa = (uint64_t)((ks >> 2) * 1024 + (ks & 3) * 2);
                        uint64_t ob = (uint64_t)((ks >> 2) * 512 + (ks & 3) * 2);
                        uint32_t en = ks > 0 ? 1u : 0u;
                        mma_bf16_n64(dbase + 0,  pd + oa, sd + ob, en);
                        mma_bf16_n64(dbase + 64, qd + oa, sd + ob, en);
                    }
                    TC_COMMIT(sbase + F_MBF + (uint32_t)(j & 3) * 8);
                }
            }
        }
    }
    __syncthreads();

    // combine halves: warp w (0-3) with warp w+4 share rows
    if (tid < 128) {
        float* cm = (float*)(smem + F_CMB);
        float m1 = cm[tid],       z1 = cm[256 + tid],       n1 = cm[512 + tid];
        float m2 = cm[tid + 128], z2 = cm[256 + tid + 128], n2 = cm[512 + tid + 128];
        float mn = fmaxf(m1, m2);
        float s1 = __expf(m1 - mn);
        float s2 = __expf(m2 - mn);
        float Zt = z1 * s1 + z2 * s2;
        float Nt = n1 * s1 + n2 * s2;
        g_rowval[b * L + p0 + tid] = Nt / Zt;
    }
    __syncthreads();
    if (tid == 0) {
        #pragma unroll
        for (int k = 0; k < 4; k++) {
            MBAR_INVAL(sbase + F_MBF + k * 8);
            MBAR_INVAL(sbase + F_MBE + k * 8);
        }
    }
    __syncthreads();
    if (wid == 0) TC_DEALLOC(tmem, 512);
#else
    // dead generic-PTX fallback (GB300 always loads the sm_103a cubin)
    if (tid < 128) {
        int p = p0 + tid;
        float psq = g_pred_sq[b * L + p];
        float pm  = ymask[b * L + p];
        float m = -INFINITY, Z = 0.f, Nv = 0.f;
        for (int s = 0; s < L; s++) {
            float cross = 0.f, tvv = 0.f;
            for (int kk = 0; kk < 128; kk++) {
                float2 a = unpack_bf(g_sy[((size_t)b * L + p) * 128 + kk]);
                float2 q = unpack_bf(g_pw[((size_t)b * L + p) * 128 + kk]);
                float2 s2 = unpack_bf(g_sx[((size_t)b * L + s) * 128 + kk]);
                cross += a.x * s2.x + a.y * s2.y;
                tvv += q.x * s2.x + q.y * s2.y;
            }
            float t = (pm * xmask[b * L + s] != 0.f) ? tvv : NEG_INF;
            float c = sqrtf(fmaxf(psq + g_src_sq[b * L + s] - 2.f * cross, 0.f));
            float mn = fmaxf(m, t);
            float sc = __expf(m - mn);
            float e = __expf(t - mn);
            Z = Z * sc + e;
            Nv = Nv * sc + e * c;
            m = mn;
        }
        g_rowval[b * L + p] = Nv / Z;
    }
#endif
}

// ---------------- kernel 5: deterministic final reduction ----------------
__global__ void finalize_kernel(const float* __restrict__ xmask,
                                const float* __restrict__ ymask,
                                float* __restrict__ out) {
    __shared__ float red[256];
    __shared__ float inv[B];
    int tid = threadIdx.x;
    int warp = tid >> 5;
    int lane = tid & 31;
    // mask sums: warp w handles batch w
    float n1 = 0.f, n2 = 0.f;
    for (int i = lane; i < L; i += 32) {
        n1 += ymask[warp * L + i];
        n2 += xmask[warp * L + i];
    }
    #pragma unroll
    for (int o = 16; o > 0; o >>= 1) {
        n1 += __shfl_down_sync(0xffffffffu, n1, o);
        n2 += __shfl_down_sync(0xffffffffu, n2, o);
    }
    if (lane == 0) inv[warp] = 1.f / (n1 * n2);

    float s = 0.f;
    for (int i = tid; i < B * L; i += 256) s += g_rowval[i];
    red[tid] = s;
    __syncthreads();
    for (int o = 128; o > 0; o >>= 1) {
        if (tid < o) red[tid] += red[tid + o];
        __syncthreads();
    }
    if (tid == 0) {
        float F = 0.f;
        for (int bb = 0; bb < B; bb++) F += inv[bb];
        out[0] = red[0] * F / (float)(B * B);
    }
}

// ---------------- launch ----------------
extern "C" void kernel_launch(void* const* d_in, const int* in_sizes, int n_in,
                              void* d_out, int out_size) {
    const float* hx = (const float*)d_in[0];
    const float* hy = (const float*)d_in[1];
    const float* xm = (const float*)d_in[2];
    const float* ym = (const float*)d_in[3];
    const float* W  = (const float*)d_in[4];
    float* out = (float*)d_out;

    cudaFuncSetAttribute(predw_kernel,
                         cudaFuncAttributeMaxDynamicSharedMemorySize, PW_SMEM);
    cudaFuncSetAttribute(fused_kernel,
                         cudaFuncAttributeMaxDynamicSharedMemorySize, F_SMEM);

    prep_kernel<<<(B * L * 32 + 255) / 256, 256>>>(hx, hy);
    wt_kernel<<<D, 128>>>(W);
    predw_kernel<<<(B * L) / 128, 128, PW_SMEM>>>();
    fused_kernel<<<B * (L / 128), 384, F_SMEM>>>(xm, ym);
    finalize_kernel<<<1, 256>>>(xm, ym, out);
}